// round 1
// baseline (speedup 1.0000x reference)
#include <cuda_runtime.h>
#include <cuda_bf16.h>

#define BB 16
#define NN 2048
#define DD 64
#define TSY 65   // padded row stride for transposed Y tiles and S tile

// Scratch (allocation-free rule: __device__ globals)
__device__ float g_y[BB * NN * DD];    // row-normalized x   (8 MB)
__device__ float g_sup[BB * NN * DD];  // support = x @ W    (8 MB)
__device__ float g_A[NN * NN];         // att * mask         (16 MB)

// ---------------------------------------------------------------------------
// Kernel A: A = att * mask  (elementwise, float4-vectorized)
// ---------------------------------------------------------------------------
__global__ void prep_A(const float* __restrict__ att, const int* __restrict__ mask) {
    int i = blockIdx.x * blockDim.x + threadIdx.x;   // float4 index, NN*NN/4 total
    float4 a = reinterpret_cast<const float4*>(att)[i];
    int4   m = reinterpret_cast<const int4*>(mask)[i];
    float4 r;
    r.x = a.x * (float)m.x;
    r.y = a.y * (float)m.y;
    r.z = a.z * (float)m.z;
    r.w = a.w * (float)m.w;
    reinterpret_cast<float4*>(g_A)[i] = r;
}

// ---------------------------------------------------------------------------
// Kernel B: per row r = b*N+n:  y = x/||x||,  sup = x @ W
// One warp per row; weight staged in smem.
// ---------------------------------------------------------------------------
__global__ void prep_xw(const float* __restrict__ x, const float* __restrict__ w) {
    __shared__ float sw[DD * DD];
    int tid = threadIdx.x;
    for (int i = tid; i < DD * DD; i += 256) sw[i] = w[i];
    __syncthreads();

    int warp = tid >> 5, lane = tid & 31;
    int row = blockIdx.x * 8 + warp;              // 4096 blocks * 8 warps = 32768 rows
    const float* xr = x + (size_t)row * DD;
    float x0 = xr[lane];
    float x1 = xr[lane + 32];

    float ss = x0 * x0 + x1 * x1;
    #pragma unroll
    for (int o = 16; o; o >>= 1) ss += __shfl_xor_sync(0xffffffffu, ss, o);
    float inv = rsqrtf(fmaxf(ss, 1e-30f));

    g_y[(size_t)row * DD + lane]      = x0 * inv;
    g_y[(size_t)row * DD + lane + 32] = x1 * inv;

    float acc0 = 0.f, acc1 = 0.f;
    #pragma unroll
    for (int d = 0; d < 32; ++d) {
        float xd = __shfl_sync(0xffffffffu, x0, d);
        acc0 = fmaf(xd, sw[d * DD + lane],      acc0);
        acc1 = fmaf(xd, sw[d * DD + lane + 32], acc1);
    }
    #pragma unroll
    for (int d = 0; d < 32; ++d) {
        float xd = __shfl_sync(0xffffffffu, x1, d);
        acc0 = fmaf(xd, sw[(d + 32) * DD + lane],      acc0);
        acc1 = fmaf(xd, sw[(d + 32) * DD + lane + 32], acc1);
    }
    g_sup[(size_t)row * DD + lane]      = acc0;
    g_sup[(size_t)row * DD + lane + 32] = acc1;
}

// ---------------------------------------------------------------------------
// Kernel C (fused, flash-style):
//   per CTA = (b, 64-row n-tile):
//     keep Yn (transposed) resident; loop over 64-row m-tiles:
//       S = Yn.Ym^T ; S *= A-tile ; O += S.V ; finally O += bias -> out.
// Micro-tile: thread (ty,tx) owns rows n = ty+16i, cols (m or e) = tx+16j.
//   -> all GEMM-phase LDS are broadcast / bank-conflict-free.
// ---------------------------------------------------------------------------
__global__ __launch_bounds__(256, 3)
void fused(const float* __restrict__ bias, float* __restrict__ out) {
    extern __shared__ float sm[];
    float* sYn = sm;                  // [d][n]  stride 65 (transposed)
    float* sYm = sYn + DD * TSY;      // [d][m]  stride 65 (transposed)
    float* sS  = sYm + DD * TSY;      // [m][n]  stride 65
    float* sV  = sS  + DD * TSY;      // [m][e]  stride 64 (float4-aligned)

    int b  = blockIdx.y;
    int n0 = blockIdx.x * 64;
    int tid = threadIdx.x;
    int tx = tid & 15, ty = tid >> 4;

    const float* yb = g_y   + (size_t)b * NN * DD;
    const float* vb = g_sup + (size_t)b * NN * DD;

    // Load Yn tile transposed into smem (one-time per CTA)
    {
        int c4 = tx * 4;
        #pragma unroll
        for (int it = 0; it < 4; ++it) {
            int r = ty + 16 * it;
            float4 v = *reinterpret_cast<const float4*>(yb + (size_t)(n0 + r) * DD + c4);
            sYn[(c4 + 0) * TSY + r] = v.x;
            sYn[(c4 + 1) * TSY + r] = v.y;
            sYn[(c4 + 2) * TSY + r] = v.z;
            sYn[(c4 + 3) * TSY + r] = v.w;
        }
    }

    float o_acc[4][4] = {};
    float bv[4];
    #pragma unroll
    for (int j = 0; j < 4; ++j) bv[j] = bias[tx + 16 * j];

    for (int m0 = 0; m0 < NN; m0 += 64) {
        __syncthreads();   // previous iter's sYm/sV/sS reads complete

        // Stage Ym (transposed) and V tiles
        {
            int c4 = tx * 4;
            #pragma unroll
            for (int it = 0; it < 4; ++it) {
                int r = ty + 16 * it;
                float4 v = *reinterpret_cast<const float4*>(yb + (size_t)(m0 + r) * DD + c4);
                sYm[(c4 + 0) * TSY + r] = v.x;
                sYm[(c4 + 1) * TSY + r] = v.y;
                sYm[(c4 + 2) * TSY + r] = v.z;
                sYm[(c4 + 3) * TSY + r] = v.w;
                float4 s = *reinterpret_cast<const float4*>(vb + (size_t)(m0 + r) * DD + c4);
                *reinterpret_cast<float4*>(sV + r * DD + c4) = s;
            }
        }

        // Prefetch A tile into registers (overlaps with S-GEMM below)
        float areg[4][4];
        #pragma unroll
        for (int i = 0; i < 4; ++i)
            #pragma unroll
            for (int j = 0; j < 4; ++j)
                areg[i][j] = g_A[(size_t)(n0 + ty + 16 * i) * NN + (m0 + tx + 16 * j)];

        __syncthreads();

        // S-GEMM: s_acc[i][j] = sum_d Yn[n][d] * Ym[m][d]
        float s_acc[4][4] = {};
        #pragma unroll 8
        for (int d = 0; d < DD; ++d) {
            float a[4], bm[4];
            #pragma unroll
            for (int i = 0; i < 4; ++i) a[i]  = sYn[d * TSY + ty + 16 * i];
            #pragma unroll
            for (int j = 0; j < 4; ++j) bm[j] = sYm[d * TSY + tx + 16 * j];
            #pragma unroll
            for (int i = 0; i < 4; ++i)
                #pragma unroll
                for (int j = 0; j < 4; ++j)
                    s_acc[i][j] = fmaf(a[i], bm[j], s_acc[i][j]);
        }

        // Apply A and stage S transposed: sS[m][n]
        #pragma unroll
        for (int i = 0; i < 4; ++i)
            #pragma unroll
            for (int j = 0; j < 4; ++j)
                sS[(tx + 16 * j) * TSY + (ty + 16 * i)] = s_acc[i][j] * areg[i][j];

        __syncthreads();

        // O-GEMM: o_acc[i][j] += sum_m sS[m][n] * sV[m][e]
        #pragma unroll 8
        for (int m = 0; m < 64; ++m) {
            float s[4], v[4];
            #pragma unroll
            for (int i = 0; i < 4; ++i) s[i] = sS[m * TSY + ty + 16 * i];
            #pragma unroll
            for (int j = 0; j < 4; ++j) v[j] = sV[m * DD + tx + 16 * j];
            #pragma unroll
            for (int i = 0; i < 4; ++i)
                #pragma unroll
                for (int j = 0; j < 4; ++j)
                    o_acc[i][j] = fmaf(s[i], v[j], o_acc[i][j]);
        }
    }

    // Epilogue: out = O + bias
    float* ob = out + (size_t)b * NN * DD + (size_t)n0 * DD;
    #pragma unroll
    for (int i = 0; i < 4; ++i)
        #pragma unroll
        for (int j = 0; j < 4; ++j)
            ob[(ty + 16 * i) * DD + tx + 16 * j] = o_acc[i][j] + bv[j];
}

// ---------------------------------------------------------------------------
extern "C" void kernel_launch(void* const* d_in, const int* in_sizes, int n_in,
                              void* d_out, int out_size) {
    const float* x    = (const float*)d_in[0];
    const float* w    = (const float*)d_in[1];
    const float* att  = (const float*)d_in[2];
    const float* bias = (const float*)d_in[3];
    const int*   mask = (const int*)d_in[4];
    float* out = (float*)d_out;

    prep_A<<<(NN * NN / 4) / 256, 256>>>(att, mask);
    prep_xw<<<(BB * NN) / 8, 256>>>(x, w);

    size_t smem = (size_t)(3 * DD * TSY + DD * DD) * sizeof(float);  // 66304 B
    cudaFuncSetAttribute(fused, cudaFuncAttributeMaxDynamicSharedMemorySize, (int)smem);
    dim3 grid(NN / 64, BB);
    fused<<<grid, 256, smem>>>(bias, out);
}

// round 6
// speedup vs baseline: 1.1511x; 1.1511x over previous
#include <cuda_runtime.h>
#include <cuda_bf16.h>
#include <cstdint>

#define BB 16
#define NN 2048
#define DD 64
#define TSY 66   // padded row stride (floats), even -> 8B alignment for float2 pairs

// Scratch (allocation-free rule: __device__ globals)
__device__ float g_y[BB * NN * DD];    // row-normalized x   (8 MB)
__device__ float g_sup[BB * NN * DD];  // support = x @ W    (8 MB)
__device__ float g_A[NN * NN];         // att * mask         (16 MB)

// ---------------- f32x2 packed-math helpers (Blackwell FFMA2 path) ---------
typedef unsigned long long ull;
__device__ __forceinline__ ull dup2(float x) {
    ull r; asm("mov.b64 %0, {%1, %1};" : "=l"(r) : "f"(x)); return r;
}
__device__ __forceinline__ void fma2(ull& d, ull a, ull b) {
    asm("fma.rn.f32x2 %0, %1, %2, %0;" : "+l"(d) : "l"(a), "l"(b));
}
__device__ __forceinline__ ull mul2(ull a, ull b) {
    ull r; asm("mul.rn.f32x2 %0, %1, %2;" : "=l"(r) : "l"(a), "l"(b)); return r;
}
__device__ __forceinline__ ull add2(ull a, ull b) {
    ull r; asm("add.rn.f32x2 %0, %1, %2;" : "=l"(r) : "l"(a), "l"(b)); return r;
}

// ---------------------------------------------------------------------------
// Kernel A: A = att * mask  (elementwise, float4-vectorized)
// ---------------------------------------------------------------------------
__global__ void prep_A(const float* __restrict__ att, const int* __restrict__ mask) {
    int i = blockIdx.x * blockDim.x + threadIdx.x;
    float4 a = reinterpret_cast<const float4*>(att)[i];
    int4   m = reinterpret_cast<const int4*>(mask)[i];
    float4 r;
    r.x = a.x * (float)m.x; r.y = a.y * (float)m.y;
    r.z = a.z * (float)m.z; r.w = a.w * (float)m.w;
    reinterpret_cast<float4*>(g_A)[i] = r;
}

// ---------------------------------------------------------------------------
// Kernel B: per row:  y = x/||x||,  sup = x @ W   (one warp per row)
// ---------------------------------------------------------------------------
__global__ void prep_xw(const float* __restrict__ x, const float* __restrict__ w) {
    __shared__ float sw[DD * DD];
    int tid = threadIdx.x;
    for (int i = tid; i < DD * DD; i += 256) sw[i] = w[i];
    __syncthreads();

    int warp = tid >> 5, lane = tid & 31;
    int row = blockIdx.x * 8 + warp;
    const float* xr = x + (size_t)row * DD;
    float x0 = xr[lane], x1 = xr[lane + 32];

    float ss = x0 * x0 + x1 * x1;
    #pragma unroll
    for (int o = 16; o; o >>= 1) ss += __shfl_xor_sync(0xffffffffu, ss, o);
    float inv = rsqrtf(fmaxf(ss, 1e-30f));

    size_t rb = (size_t)row * DD;
    g_y[rb + lane]      = x0 * inv;
    g_y[rb + lane + 32] = x1 * inv;

    float a0 = 0.f, a1 = 0.f;
    #pragma unroll
    for (int d = 0; d < 32; ++d) {
        float xd = __shfl_sync(0xffffffffu, x0, d);
        a0 = fmaf(xd, sw[d * DD + lane],      a0);
        a1 = fmaf(xd, sw[d * DD + lane + 32], a1);
    }
    #pragma unroll
    for (int d = 0; d < 32; ++d) {
        float xd = __shfl_sync(0xffffffffu, x1, d);
        a0 = fmaf(xd, sw[(d + 32) * DD + lane],      a0);
        a1 = fmaf(xd, sw[(d + 32) * DD + lane + 32], a1);
    }
    g_sup[rb + lane]      = a0;
    g_sup[rb + lane + 32] = a1;
}

// ---------------------------------------------------------------------------
// Kernel C (fused, flash-style, FFMA2):
//   per CTA = (b, 64-row n-tile); loop over 64-row m-tiles:
//     S = Yn.Ym^T ; P = A*S ; O += P.V ; finally O += bias -> out.
// Thread (ty,tx): n rows {ty+16i}, m/e col PAIRS {2tx,2tx+1} and {2tx+32,2tx+33}.
// Paired operands load as single LDS.64; scalar operands broadcast + dup2.
// ---------------------------------------------------------------------------
__global__ __launch_bounds__(256, 3)
void fused(const float* __restrict__ bias, float* __restrict__ out) {
    extern __shared__ float sm[];
    float* sYn = sm;                  // [d][n]  stride 66 (transposed)
    float* sYm = sYn + DD * TSY;      // [d][m]  stride 66 (transposed)
    float* sS  = sYm + DD * TSY;      // [n][m]  stride 66 (pair-contiguous in m)
    float* sV  = sS  + DD * TSY;      // [m][e]  stride 64

    int b  = blockIdx.y;
    int n0 = blockIdx.x * 64;
    int tid = threadIdx.x;
    int tx = tid & 15, ty = tid >> 4;
    int tx2 = 2 * tx;

    const float* yb = g_y   + (size_t)b * NN * DD;
    const float* vb = g_sup + (size_t)b * NN * DD;

    // Load Yn tile transposed into smem (one-time per CTA)
    {
        int c4 = tx * 4;
        #pragma unroll
        for (int it = 0; it < 4; ++it) {
            int r = ty + 16 * it;
            float4 v = *reinterpret_cast<const float4*>(yb + (size_t)(n0 + r) * DD + c4);
            sYn[(c4 + 0) * TSY + r] = v.x;
            sYn[(c4 + 1) * TSY + r] = v.y;
            sYn[(c4 + 2) * TSY + r] = v.z;
            sYn[(c4 + 3) * TSY + r] = v.w;
        }
    }

    ull o_acc[4][2] = {};
    ull bp[2];
    bp[0] = *reinterpret_cast<const ull*>(bias + tx2);
    bp[1] = *reinterpret_cast<const ull*>(bias + tx2 + 32);

    for (int m0 = 0; m0 < NN; m0 += 64) {
        __syncthreads();   // previous iter's sYm/sV/sS reads complete

        // Stage Ym (transposed) and V tiles
        {
            int c4 = tx * 4;
            #pragma unroll
            for (int it = 0; it < 4; ++it) {
                int r = ty + 16 * it;
                float4 v = *reinterpret_cast<const float4*>(yb + (size_t)(m0 + r) * DD + c4);
                sYm[(c4 + 0) * TSY + r] = v.x;
                sYm[(c4 + 1) * TSY + r] = v.y;
                sYm[(c4 + 2) * TSY + r] = v.z;
                sYm[(c4 + 3) * TSY + r] = v.w;
                float4 s = *reinterpret_cast<const float4*>(vb + (size_t)(m0 + r) * DD + c4);
                *reinterpret_cast<float4*>(sV + r * DD + c4) = s;
            }
        }

        // Prefetch A pairs (gmem, L2-resident; overlaps with stage/sync)
        ull apair[4][2];
        #pragma unroll
        for (int i = 0; i < 4; ++i) {
            const float* ar = g_A + (size_t)(n0 + ty + 16 * i) * NN + m0;
            apair[i][0] = *reinterpret_cast<const ull*>(ar + tx2);
            apair[i][1] = *reinterpret_cast<const ull*>(ar + tx2 + 32);
        }

        __syncthreads();

        // S-GEMM (FFMA2): s_acc[i][jp] = sum_d Yn[d][n_i] * Ym[d][mpair_jp]
        ull s_acc[4][2] = {};
        #pragma unroll 8
        for (int d = 0; d < DD; ++d) {
            const float* rn = sYn + d * TSY;
            const float* rm = sYm + d * TSY;
            ull b0 = *reinterpret_cast<const ull*>(rm + tx2);
            ull b1 = *reinterpret_cast<const ull*>(rm + tx2 + 32);
            #pragma unroll
            for (int i = 0; i < 4; ++i) {
                ull ad = dup2(rn[ty + 16 * i]);
                fma2(s_acc[i][0], ad, b0);
                fma2(s_acc[i][1], ad, b1);
            }
        }

        // P = A*S, stage to sS [n][m] (pair-contiguous m -> STS.64)
        #pragma unroll
        for (int i = 0; i < 4; ++i) {
            float* rowp = sS + (ty + 16 * i) * TSY;
            *reinterpret_cast<ull*>(rowp + tx2)      = mul2(s_acc[i][0], apair[i][0]);
            *reinterpret_cast<ull*>(rowp + tx2 + 32) = mul2(s_acc[i][1], apair[i][1]);
        }

        __syncthreads();

        // O-GEMM (FFMA2): o_acc[i][jp] += sum_m P[n_i][m] * V[m][epair_jp]
        #pragma unroll 8
        for (int mm = 0; mm < 64; ++mm) {
            const float* rv = sV + mm * DD;
            ull v0 = *reinterpret_cast<const ull*>(rv + tx2);
            ull v1 = *reinterpret_cast<const ull*>(rv + tx2 + 32);
            #pragma unroll
            for (int i = 0; i < 4; ++i) {
                ull sd = dup2(sS[(ty + 16 * i) * TSY + mm]);
                fma2(o_acc[i][0], sd, v0);
                fma2(o_acc[i][1], sd, v1);
            }
        }
    }

    // Epilogue: out = O + bias  (64-bit stores)
    float* ob = out + ((size_t)b * NN + n0) * DD;
    #pragma unroll
    for (int i = 0; i < 4; ++i) {
        float* rowp = ob + (ty + 16 * i) * DD;
        *reinterpret_cast<ull*>(rowp + tx2)      = add2(o_acc[i][0], bp[0]);
        *reinterpret_cast<ull*>(rowp + tx2 + 32) = add2(o_acc[i][1], bp[1]);
    }
}

// ---------------------------------------------------------------------------
extern "C" void kernel_launch(void* const* d_in, const int* in_sizes, int n_in,
                              void* d_out, int out_size) {
    const float* x    = (const float*)d_in[0];
    const float* w    = (const float*)d_in[1];
    const float* att  = (const float*)d_in[2];
    const float* bias = (const float*)d_in[3];
    const int*   mask = (const int*)d_in[4];
    float* out = (float*)d_out;

    prep_A<<<(NN * NN / 4) / 256, 256>>>(att, mask);
    prep_xw<<<(BB * NN) / 8, 256>>>(x, w);

    size_t smem = (size_t)(3 * DD * TSY + DD * DD) * sizeof(float);  // 67072 B
    cudaFuncSetAttribute(fused, cudaFuncAttributeMaxDynamicSharedMemorySize, (int)smem);
    dim3 grid(NN / 64, BB);
    fused<<<grid, 256, smem>>>(bias, out);
}

// round 7
// speedup vs baseline: 1.4633x; 1.2712x over previous
#include <cuda_runtime.h>
#include <cuda_bf16.h>
#include <cstdint>

#define BB 16
#define NN 2048
#define DD 64
#define TSN 130   // stride for [d][n] / [m][n] tiles (128 n + 2 pad, even)
#define TSM 66    // stride for [d][m] tile (64 m + 2 pad, even)

// Scratch (allocation-free rule: __device__ globals)
__device__ float g_y[BB * NN * DD];    // row-normalized x         (8 MB)
__device__ float g_sup[BB * NN * DD];  // support = x @ W          (8 MB)
__device__ float g_At[NN * NN];        // (att*mask) TRANSPOSED    (16 MB)

// ---------------- f32x2 packed-math helpers --------------------------------
typedef unsigned long long ull;
__device__ __forceinline__ ull dup2(float x) {
    ull r; asm("mov.b64 %0, {%1, %1};" : "=l"(r) : "f"(x)); return r;
}
__device__ __forceinline__ void unpk(ull v, float& lo, float& hi) {
    asm("mov.b64 {%0, %1}, %2;" : "=f"(lo), "=f"(hi) : "l"(v));
}
__device__ __forceinline__ void fma2(ull& d, ull a, ull b) {
    asm("fma.rn.f32x2 %0, %1, %2, %0;" : "+l"(d) : "l"(a), "l"(b));
}
__device__ __forceinline__ ull mul2(ull a, ull b) {
    ull r; asm("mul.rn.f32x2 %0, %1, %2;" : "=l"(r) : "l"(a), "l"(b)); return r;
}
__device__ __forceinline__ ull add2(ull a, ull b) {
    ull r; asm("add.rn.f32x2 %0, %1, %2;" : "=l"(r) : "l"(a), "l"(b)); return r;
}

// ---------------------------------------------------------------------------
// Kernel A: g_At[m][n] = att[n][m] * mask[n][m]   (32x32 smem transpose)
// ---------------------------------------------------------------------------
__global__ void prep_At(const float* __restrict__ att, const int* __restrict__ mask) {
    __shared__ float t[32][33];
    int n0 = blockIdx.x * 32, m0 = blockIdx.y * 32;
    int lx = threadIdx.x & 31, ly = threadIdx.x >> 5;   // 32 x 8
    #pragma unroll
    for (int s = 0; s < 32; s += 8) {
        size_t idx = (size_t)(n0 + ly + s) * NN + m0 + lx;
        t[ly + s][lx] = att[idx] * (float)mask[idx];
    }
    __syncthreads();
    #pragma unroll
    for (int s = 0; s < 32; s += 8) {
        g_At[(size_t)(m0 + ly + s) * NN + n0 + lx] = t[lx][ly + s];
    }
}

// ---------------------------------------------------------------------------
// Kernel B: per row:  y = x/||x||,  sup = x @ W   (one warp per row)
// ---------------------------------------------------------------------------
__global__ void prep_xw(const float* __restrict__ x, const float* __restrict__ w) {
    __shared__ float sw[DD * DD];
    int tid = threadIdx.x;
    for (int i = tid; i < DD * DD; i += 256) sw[i] = w[i];
    __syncthreads();

    int warp = tid >> 5, lane = tid & 31;
    int row = blockIdx.x * 8 + warp;
    const float* xr = x + (size_t)row * DD;
    float x0 = xr[lane], x1 = xr[lane + 32];

    float ss = x0 * x0 + x1 * x1;
    #pragma unroll
    for (int o = 16; o; o >>= 1) ss += __shfl_xor_sync(0xffffffffu, ss, o);
    float inv = rsqrtf(fmaxf(ss, 1e-30f));

    size_t rb = (size_t)row * DD;
    g_y[rb + lane]      = x0 * inv;
    g_y[rb + lane + 32] = x1 * inv;

    float a0 = 0.f, a1 = 0.f;
    #pragma unroll
    for (int d = 0; d < 32; ++d) {
        float xd = __shfl_sync(0xffffffffu, x0, d);
        a0 = fmaf(xd, sw[d * DD + lane],      a0);
        a1 = fmaf(xd, sw[d * DD + lane + 32], a1);
    }
    #pragma unroll
    for (int d = 0; d < 32; ++d) {
        float xd = __shfl_sync(0xffffffffu, x1, d);
        a0 = fmaf(xd, sw[(d + 32) * DD + lane],      a0);
        a1 = fmaf(xd, sw[(d + 32) * DD + lane + 32], a1);
    }
    g_sup[rb + lane]      = a0;
    g_sup[rb + lane + 32] = a1;
}

// ---------------------------------------------------------------------------
// Kernel C (fused, FFMA2, 1-wavefront inner loops):
//   CTA = (b, 128-row n-tile); loop over 64-row m-chunks:
//     S = Yn.Ym^T ; P = At*S ; O += P.V ; epilogue O + bias.
// Thread: n-PAIRS at {2tx+32k', +1} (k'=0..3, 8 rows, packed in f32x2 lanes),
//         m/e scalars {2ty, 2ty+1, 2ty+32, 2ty+33} (loaded as pairs, unpacked+dup'd).
// ---------------------------------------------------------------------------
__global__ __launch_bounds__(256, 2)
void fused(const float* __restrict__ bias, float* __restrict__ out) {
    extern __shared__ float sm[];
    float* sYn = sm;                   // [d][n] stride 130  (8320 f)
    float* sYm = sYn + DD * TSN;       // [d][m] stride 66   (4224 f)
    float* sS  = sYm + DD * TSM;       // [m][n] stride 130  (8320 f)
    float* sV  = sS  + DD * TSN;       // [m][e] stride 64   (4096 f)

    int b  = blockIdx.y;
    int n0 = blockIdx.x * 128;
    int tid = threadIdx.x;
    int tx = tid & 15, ty = tid >> 4;
    int tx2 = 2 * tx, ty2 = 2 * ty;
    int c4 = 4 * tx;

    const float* yb = g_y   + (size_t)b * NN * DD;
    const float* vb = g_sup + (size_t)b * NN * DD;

    // Stage Yn tile (128 x 64) transposed -> sYn[d][n]  (one-time)
    #pragma unroll
    for (int it = 0; it < 8; ++it) {
        int r = ty + 16 * it;
        float4 v = *reinterpret_cast<const float4*>(yb + (size_t)(n0 + r) * DD + c4);
        sYn[(c4 + 0) * TSN + r] = v.x;
        sYn[(c4 + 1) * TSN + r] = v.y;
        sYn[(c4 + 2) * TSN + r] = v.z;
        sYn[(c4 + 3) * TSN + r] = v.w;
    }

    ull o_acc[4][4] = {};   // [n-pair k'][e scalar j]

    for (int m0 = 0; m0 < NN; m0 += 64) {
        __syncthreads();   // previous O-GEMM reads of sYm/sV/sS complete

        // Stage Ym (64 x 64) transposed -> sYm[d][m]
        #pragma unroll
        for (int it = 0; it < 4; ++it) {
            int r = ty + 16 * it;
            float4 v = *reinterpret_cast<const float4*>(yb + (size_t)(m0 + r) * DD + c4);
            sYm[(c4 + 0) * TSM + r] = v.x;
            sYm[(c4 + 1) * TSM + r] = v.y;
            sYm[(c4 + 2) * TSM + r] = v.z;
            sYm[(c4 + 3) * TSM + r] = v.w;
        }
        // Stage V (64 x 64) -> sV[m][e]  (coalesced both sides)
        #pragma unroll
        for (int k = 0; k < 4; ++k) {
            int idx = tid + k * 256;
            int r = idx >> 4, c = (idx & 15) * 4;
            *reinterpret_cast<float4*>(sV + r * DD + c) =
                *reinterpret_cast<const float4*>(vb + (size_t)(m0 + r) * DD + c);
        }
        __syncthreads();

        // ---- S-GEMM: s_acc[k'][j] (+= over d)  a=(n,n+1) pair, b=dup(m) ----
        ull s_acc[4][4] = {};
        #pragma unroll 4
        for (int d = 0; d < DD; ++d) {
            const float* rn = sYn + d * TSN;
            const float* rm = sYm + d * TSM;
            ull a0 = *reinterpret_cast<const ull*>(rn + tx2);
            ull a1 = *reinterpret_cast<const ull*>(rn + tx2 + 32);
            ull a2 = *reinterpret_cast<const ull*>(rn + tx2 + 64);
            ull a3 = *reinterpret_cast<const ull*>(rn + tx2 + 96);
            ull mp0 = *reinterpret_cast<const ull*>(rm + ty2);
            ull mp1 = *reinterpret_cast<const ull*>(rm + ty2 + 32);
            float m0f, m1f, m2f, m3f;
            unpk(mp0, m0f, m1f);
            unpk(mp1, m2f, m3f);
            ull bd[4] = { dup2(m0f), dup2(m1f), dup2(m2f), dup2(m3f) };
            #pragma unroll
            for (int j = 0; j < 4; ++j) {
                fma2(s_acc[0][j], a0, bd[j]);
                fma2(s_acc[1][j], a1, bd[j]);
                fma2(s_acc[2][j], a2, bd[j]);
                fma2(s_acc[3][j], a3, bd[j]);
            }
        }

        // ---- P = At * S -> sS[m][n]  (At coalesced LDG.64, STS.64 pairs) ----
        #pragma unroll
        for (int j = 0; j < 4; ++j) {
            int mv = (j < 2) ? (ty2 + j) : (ty2 + 30 + j);   // {2ty,2ty+1,2ty+32,2ty+33}
            const float* ar = g_At + (size_t)(m0 + mv) * NN + n0;
            float* srow = sS + mv * TSN;
            #pragma unroll
            for (int k = 0; k < 4; ++k) {
                ull ap = *reinterpret_cast<const ull*>(ar + tx2 + 32 * k);
                *reinterpret_cast<ull*>(srow + tx2 + 32 * k) = mul2(s_acc[k][j], ap);
            }
        }
        __syncthreads();

        // ---- O-GEMM: o_acc[k'][j] += P-pair[k'] * dup(V[m][e_j]) ----
        #pragma unroll 4
        for (int mm = 0; mm < 64; ++mm) {
            const float* rp = sS + mm * TSN;
            const float* rv = sV + mm * DD;
            ull p0 = *reinterpret_cast<const ull*>(rp + tx2);
            ull p1 = *reinterpret_cast<const ull*>(rp + tx2 + 32);
            ull p2 = *reinterpret_cast<const ull*>(rp + tx2 + 64);
            ull p3 = *reinterpret_cast<const ull*>(rp + tx2 + 96);
            ull vp0 = *reinterpret_cast<const ull*>(rv + ty2);
            ull vp1 = *reinterpret_cast<const ull*>(rv + ty2 + 32);
            float v0f, v1f, v2f, v3f;
            unpk(vp0, v0f, v1f);
            unpk(vp1, v2f, v3f);
            ull vd[4] = { dup2(v0f), dup2(v1f), dup2(v2f), dup2(v3f) };
            #pragma unroll
            for (int j = 0; j < 4; ++j) {
                fma2(o_acc[0][j], p0, vd[j]);
                fma2(o_acc[1][j], p1, vd[j]);
                fma2(o_acc[2][j], p2, vd[j]);
                fma2(o_acc[3][j], p3, vd[j]);
            }
        }
    }

    // ---- Epilogue: out[n][e] = O + bias  (acc lo -> row n, hi -> row n+1) ----
    float* ob = out + ((size_t)b * NN + n0) * DD;
    #pragma unroll
    for (int j = 0; j < 4; ++j) {
        int ev = (j < 2) ? (ty2 + j) : (ty2 + 30 + j);
        float bj = bias[ev];
        #pragma unroll
        for (int k = 0; k < 4; ++k) {
            int n = tx2 + 32 * k;
            float lo, hi;
            unpk(o_acc[k][j], lo, hi);
            ob[(size_t)n * DD + ev]       = lo + bj;
            ob[(size_t)(n + 1) * DD + ev] = hi + bj;
        }
    }
}

// ---------------------------------------------------------------------------
extern "C" void kernel_launch(void* const* d_in, const int* in_sizes, int n_in,
                              void* d_out, int out_size) {
    const float* x    = (const float*)d_in[0];
    const float* w    = (const float*)d_in[1];
    const float* att  = (const float*)d_in[2];
    const float* bias = (const float*)d_in[3];
    const int*   mask = (const int*)d_in[4];
    float* out = (float*)d_out;

    prep_At<<<dim3(NN / 32, NN / 32), 256>>>(att, mask);
    prep_xw<<<(BB * NN) / 8, 256>>>(x, w);

    size_t smem = (size_t)(DD * TSN + DD * TSM + DD * TSN + DD * DD) * sizeof(float); // 99840 B
    cudaFuncSetAttribute(fused, cudaFuncAttributeMaxDynamicSharedMemorySize, (int)smem);
    dim3 grid(NN / 128, BB);
    fused<<<grid, 256, smem>>>(bias, out);
}

// round 9
// speedup vs baseline: 1.8256x; 1.2476x over previous
#include <cuda_runtime.h>
#include <cuda_bf16.h>
#include <cstdint>

#define BB 16
#define NN 2048
#define DD 64
#define TSN 130        // sS row stride in floats (128 n + 2 pad)

// bf16 smem row stride for Y tiles: 64 data + 8 pad = 72 bf16 = 144 bytes
#define YSTR 144

// ---------------- scratch (__device__ globals) -----------------------------
__device__ __nv_bfloat16 g_yh[BB * NN * DD];   // normalized x, bf16 hi (4 MB)
__device__ __nv_bfloat16 g_yl[BB * NN * DD];   // normalized x, bf16 lo (4 MB)
__device__ float         g_sup[BB * NN * DD];  // support = x @ W       (8 MB)
__device__ float         g_A[NN * NN];         // att * mask            (16 MB)

// ---------------- smem byte offsets ---------------------------------------
#define OFF_YNH 0          // 128 x 72 bf16   18432
#define OFF_YNL 18432      //                 18432
#define OFF_YMH 36864      //  64 x 72 bf16    9216
#define OFF_YML 46080      //                  9216
#define OFF_SS  55296      //  64 x 130 f32   33280
#define OFF_SV  88576      //  64 x 64  f32   16384
#define SMEM_BYTES 104960

// ---------------- f32x2 helpers (O-GEMM FFMA2 path) ------------------------
typedef unsigned long long ull;
__device__ __forceinline__ ull dup2(float x) {
    ull r; asm("mov.b64 %0, {%1, %1};" : "=l"(r) : "f"(x)); return r;
}
__device__ __forceinline__ void unpk(ull v, float& lo, float& hi) {
    asm("mov.b64 {%0, %1}, %2;" : "=f"(lo), "=f"(hi) : "l"(v));
}
__device__ __forceinline__ void fma2(ull& d, ull a, ull b) {
    asm("fma.rn.f32x2 %0, %1, %2, %0;" : "+l"(d) : "l"(a), "l"(b));
}

// ---------------- tensor helpers -------------------------------------------
__device__ __forceinline__ uint32_t su32(const void* p) {
    uint32_t a;
    asm("{ .reg .u64 t; cvta.to.shared.u64 t, %1; cvt.u32.u64 %0, t; }" : "=r"(a) : "l"(p));
    return a;
}
#define LDMX4(r, addr)                                                        \
    asm volatile("ldmatrix.sync.aligned.m8n8.x4.shared.b16 {%0,%1,%2,%3}, [%4];" \
        : "=r"((r)[0]), "=r"((r)[1]), "=r"((r)[2]), "=r"((r)[3]) : "r"(addr))
#define MMA_BF16(c, a, b0, b1)                                                \
    asm volatile("mma.sync.aligned.m16n8k16.row.col.f32.bf16.bf16.f32 "       \
        "{%0,%1,%2,%3}, {%4,%5,%6,%7}, {%8,%9}, {%0,%1,%2,%3};"               \
        : "+f"((c)[0]), "+f"((c)[1]), "+f"((c)[2]), "+f"((c)[3])              \
        : "r"((a)[0]), "r"((a)[1]), "r"((a)[2]), "r"((a)[3]), "r"(b0), "r"(b1))

// ---------------------------------------------------------------------------
// Kernel A: A = att * mask
// ---------------------------------------------------------------------------
__global__ void prep_A(const float* __restrict__ att, const int* __restrict__ mask) {
    int i = blockIdx.x * blockDim.x + threadIdx.x;
    float4 a = reinterpret_cast<const float4*>(att)[i];
    int4   m = reinterpret_cast<const int4*>(mask)[i];
    float4 r;
    r.x = a.x * (float)m.x; r.y = a.y * (float)m.y;
    r.z = a.z * (float)m.z; r.w = a.w * (float)m.w;
    reinterpret_cast<float4*>(g_A)[i] = r;
}

// ---------------------------------------------------------------------------
// Kernel B: y = x/||x|| -> bf16 hi/lo ; sup = x @ W  (one warp per row)
// ---------------------------------------------------------------------------
__global__ void prep_xw(const float* __restrict__ x, const float* __restrict__ w) {
    __shared__ float sw[DD * DD];
    int tid = threadIdx.x;
    for (int i = tid; i < DD * DD; i += 256) sw[i] = w[i];
    __syncthreads();

    int warp = tid >> 5, lane = tid & 31;
    int row = blockIdx.x * 8 + warp;
    const float* xr = x + (size_t)row * DD;
    float x0 = xr[lane], x1 = xr[lane + 32];

    float ss = x0 * x0 + x1 * x1;
    #pragma unroll
    for (int o = 16; o; o >>= 1) ss += __shfl_xor_sync(0xffffffffu, ss, o);
    float inv = rsqrtf(fmaxf(ss, 1e-30f));

    float y0 = x0 * inv, y1 = x1 * inv;
    __nv_bfloat16 h0 = __float2bfloat16(y0), h1 = __float2bfloat16(y1);
    size_t rb = (size_t)row * DD;
    g_yh[rb + lane]      = h0;
    g_yh[rb + lane + 32] = h1;
    g_yl[rb + lane]      = __float2bfloat16(y0 - __bfloat162float(h0));
    g_yl[rb + lane + 32] = __float2bfloat16(y1 - __bfloat162float(h1));

    float a0 = 0.f, a1 = 0.f;
    #pragma unroll
    for (int d = 0; d < 32; ++d) {
        float xd = __shfl_sync(0xffffffffu, x0, d);
        a0 = fmaf(xd, sw[d * DD + lane],      a0);
        a1 = fmaf(xd, sw[d * DD + lane + 32], a1);
    }
    #pragma unroll
    for (int d = 0; d < 32; ++d) {
        float xd = __shfl_sync(0xffffffffu, x1, d);
        a0 = fmaf(xd, sw[(d + 32) * DD + lane],      a0);
        a1 = fmaf(xd, sw[(d + 32) * DD + lane + 32], a1);
    }
    g_sup[rb + lane]      = a0;
    g_sup[rb + lane + 32] = a1;
}

// ---------------------------------------------------------------------------
// Kernel C: S via mma.sync bf16-split (tensor), P = A*S, O += P.V (FFMA2)
//   CTA = (b, 128n tile); chunks of 64 m.
//   Warp w: wn = w&3 (n-subtile 32), wm = w>>2 (m-subtile 32).
// ---------------------------------------------------------------------------
__global__ __launch_bounds__(256, 2)
void fused(const float* __restrict__ bias, float* __restrict__ out) {
    extern __shared__ char smc[];
    uint32_t sb = su32(smc);
    float* sS = reinterpret_cast<float*>(smc + OFF_SS);
    float* sV = reinterpret_cast<float*>(smc + OFF_SV);

    int b  = blockIdx.y;
    int n0 = blockIdx.x * 128;
    int tid = threadIdx.x;
    int w = tid >> 5, lane = tid & 31;
    int tx = tid & 15, ty = tid >> 4;
    int tx2 = 2 * tx, ty2 = 2 * ty;
    int wn = w & 3, wm = w >> 2;
    int n0w = wn * 32, m0w = wm * 32;

    const __nv_bfloat16* yhB = g_yh + (size_t)b * NN * DD;
    const __nv_bfloat16* ylB = g_yl + (size_t)b * NN * DD;
    const float*         vb  = g_sup + (size_t)b * NN * DD;

    // Stage Yn tile (128 x 64 bf16 hi/lo), padded rows (one-time)
    #pragma unroll
    for (int k = 0; k < 4; ++k) {
        int idx = tid + k * 256;                 // 1024 uint4 per matrix
        int r = idx >> 3, c = idx & 7;
        *reinterpret_cast<uint4*>(smc + OFF_YNH + r * YSTR + c * 16) =
            *reinterpret_cast<const uint4*>(yhB + (size_t)(n0 + r) * DD + c * 8);
        *reinterpret_cast<uint4*>(smc + OFF_YNL + r * YSTR + c * 16) =
            *reinterpret_cast<const uint4*>(ylB + (size_t)(n0 + r) * DD + c * 8);
    }

    // ldmatrix lane addressing (shared by A and B frags)
    int lrow = lane & 7, sub = lane >> 3;
    int rowoff = (sub & 1) * 8 + lrow;           // row within 16-row group
    int koffb  = (sub >> 1) * 16;                // 8-elem k offset in bytes

    ull o_acc[4][4] = {};   // [n-pair k'][e scalar j]  (R7 layout)

    for (int m0 = 0; m0 < NN; m0 += 64) {
        __syncthreads();   // previous O-phase reads of sYm/sV/sS done

        // Stage Ym (64 x 64 bf16 hi/lo) + V (64 x 64 f32)
        #pragma unroll
        for (int k = 0; k < 2; ++k) {
            int idx = tid + k * 256;             // 512 uint4 per matrix
            int r = idx >> 3, c = idx & 7;
            *reinterpret_cast<uint4*>(smc + OFF_YMH + r * YSTR + c * 16) =
                *reinterpret_cast<const uint4*>(yhB + (size_t)(m0 + r) * DD + c * 8);
            *reinterpret_cast<uint4*>(smc + OFF_YML + r * YSTR + c * 16) =
                *reinterpret_cast<const uint4*>(ylB + (size_t)(m0 + r) * DD + c * 8);
        }
        #pragma unroll
        for (int k = 0; k < 4; ++k) {
            int idx = tid + k * 256;
            int r = idx >> 4, c = (idx & 15) * 4;
            *reinterpret_cast<float4*>(sV + r * DD + c) =
                *reinterpret_cast<const float4*>(vb + (size_t)(m0 + r) * DD + c);
        }
        __syncthreads();

        // ---- S-phase: tensor mma, bf16 split (HH + HL + LH) ----
        float cfr[2][4][4];
        #pragma unroll
        for (int i = 0; i < 2; ++i)
            #pragma unroll
            for (int j = 0; j < 4; ++j)
                #pragma unroll
                for (int q = 0; q < 4; ++q) cfr[i][j][q] = 0.f;

        #pragma unroll
        for (int ks = 0; ks < 4; ++ks) {
            int kb = ks * 32 + koffb;
            uint32_t aH[2][4], aL[2][4], bH[2][4], bL[2][4];
            #pragma unroll
            for (int i = 0; i < 2; ++i) {
                uint32_t ra = (uint32_t)((n0w + i * 16 + rowoff) * YSTR + kb);
                LDMX4(aH[i], sb + OFF_YNH + ra);
                LDMX4(aL[i], sb + OFF_YNL + ra);
            }
            #pragma unroll
            for (int j16 = 0; j16 < 2; ++j16) {
                uint32_t rb2 = (uint32_t)((m0w + j16 * 16 + rowoff) * YSTR + kb);
                LDMX4(bH[j16], sb + OFF_YMH + rb2);
                LDMX4(bL[j16], sb + OFF_YML + rb2);
            }
            #pragma unroll
            for (int i = 0; i < 2; ++i)
                #pragma unroll
                for (int mt = 0; mt < 4; ++mt) {
                    int j16 = mt >> 1, par = mt & 1;
                    MMA_BF16(cfr[i][mt], aH[i], bH[j16][par], bH[j16][par + 2]);
                    MMA_BF16(cfr[i][mt], aH[i], bL[j16][par], bL[j16][par + 2]);
                    MMA_BF16(cfr[i][mt], aL[i], bH[j16][par], bH[j16][par + 2]);
                }
        }

        // ---- P-phase: P = A * S -> sS[m][n]  (local indices) ----
        int t4 = lane >> 2, tm2 = (lane & 3) * 2;
        #pragma unroll
        for (int i = 0; i < 2; ++i) {
            #pragma unroll
            for (int mt = 0; mt < 4; ++mt) {
                int nfl = n0w + i * 16 + t4;       // local n (row of S)
                int mfl = m0w + mt * 8 + tm2;      // local m (col pair)
                const float* ar = g_A + (size_t)(n0 + nfl) * NN + (m0 + mfl);
                ull ap0 = *reinterpret_cast<const ull*>(ar);
                ull ap1 = *reinterpret_cast<const ull*>(ar + 8 * NN);
                float a0, a1, a2, a3;
                unpk(ap0, a0, a1);
                unpk(ap1, a2, a3);
                sS[mfl * TSN + nfl]           = cfr[i][mt][0] * a0;
                sS[(mfl + 1) * TSN + nfl]     = cfr[i][mt][1] * a1;
                sS[mfl * TSN + nfl + 8]       = cfr[i][mt][2] * a2;
                sS[(mfl + 1) * TSN + nfl + 8] = cfr[i][mt][3] * a3;
            }
        }
        __syncthreads();

        // ---- O-phase (R7 FFMA2): o_acc += P-pair * dup(V) ----
        #pragma unroll 4
        for (int mm = 0; mm < 64; ++mm) {
            const float* rp = sS + mm * TSN;
            const float* rv = sV + mm * DD;
            ull p0 = *reinterpret_cast<const ull*>(rp + tx2);
            ull p1 = *reinterpret_cast<const ull*>(rp + tx2 + 32);
            ull p2 = *reinterpret_cast<const ull*>(rp + tx2 + 64);
            ull p3 = *reinterpret_cast<const ull*>(rp + tx2 + 96);
            ull vp0 = *reinterpret_cast<const ull*>(rv + ty2);
            ull vp1 = *reinterpret_cast<const ull*>(rv + ty2 + 32);
            float v0f, v1f, v2f, v3f;
            unpk(vp0, v0f, v1f);
            unpk(vp1, v2f, v3f);
            ull vd[4] = { dup2(v0f), dup2(v1f), dup2(v2f), dup2(v3f) };
            #pragma unroll
            for (int j = 0; j < 4; ++j) {
                fma2(o_acc[0][j], p0, vd[j]);
                fma2(o_acc[1][j], p1, vd[j]);
                fma2(o_acc[2][j], p2, vd[j]);
                fma2(o_acc[3][j], p3, vd[j]);
            }
        }
    }

    // ---- Epilogue: out[n][e] = O + bias ----
    float* ob = out + ((size_t)b * NN + n0) * DD;
    #pragma unroll
    for (int j = 0; j < 4; ++j) {
        int ev = (j < 2) ? (ty2 + j) : (ty2 + 30 + j);
        float bj = bias[ev];
        #pragma unroll
        for (int k = 0; k < 4; ++k) {
            int n = tx2 + 32 * k;
            float lo, hi;
            unpk(o_acc[k][j], lo, hi);
            ob[(size_t)n * DD + ev]       = lo + bj;
            ob[(size_t)(n + 1) * DD + ev] = hi + bj;
        }
    }
}

// ---------------------------------------------------------------------------
extern "C" void kernel_launch(void* const* d_in, const int* in_sizes, int n_in,
                              void* d_out, int out_size) {
    const float* x    = (const float*)d_in[0];
    const float* w    = (const float*)d_in[1];
    const float* att  = (const float*)d_in[2];
    const float* bias = (const float*)d_in[3];
    const int*   mask = (const int*)d_in[4];
    float* out = (float*)d_out;

    prep_A<<<(NN * NN / 4) / 256, 256>>>(att, mask);
    prep_xw<<<(BB * NN) / 8, 256>>>(x, w);

    cudaFuncSetAttribute(fused, cudaFuncAttributeMaxDynamicSharedMemorySize, SMEM_BYTES);
    dim3 grid(NN / 128, BB);
    fused<<<grid, 256, SMEM_BYTES>>>(bias, out);
}

// round 10
// speedup vs baseline: 2.9759x; 1.6301x over previous
#include <cuda_runtime.h>
#include <cuda_bf16.h>
#include <cstdint>

#define BB 16
#define NN 2048
#define DD 64
#define YSTR 144       // bf16 tile row stride bytes (64 data + 8 pad = 72 bf16)

// ---------------- scratch (__device__ globals) -----------------------------
__device__ __nv_bfloat16 g_yh[BB * NN * DD];   // normalized x, bf16 hi
__device__ __nv_bfloat16 g_yl[BB * NN * DD];   // normalized x, bf16 lo
__device__ __nv_bfloat16 g_vh[BB * NN * DD];   // support = x@W, bf16 hi
__device__ __nv_bfloat16 g_vl[BB * NN * DD];   // support = x@W, bf16 lo
__device__ float         g_A[NN * NN];         // att * mask

// ---------------- smem byte offsets ---------------------------------------
#define OFF_YNH 0          // 128 x 72 bf16   18432
#define OFF_YNL 18432      //                 18432
#define OFF_YMH 36864      //  64 x 72 bf16    9216
#define OFF_YML 46080      //                  9216
#define OFF_VH  55296      //  64 x 72 bf16    9216
#define OFF_VL  64512      //                  9216
#define OFF_PH  73728      // 128 x 72 bf16   18432
#define OFF_PL  92160      //                 18432
#define SMEM_BYTES 110592

typedef unsigned long long ull;
__device__ __forceinline__ void unpk(ull v, float& lo, float& hi) {
    asm("mov.b64 {%0, %1}, %2;" : "=f"(lo), "=f"(hi) : "l"(v));
}
__device__ __forceinline__ uint32_t su32(const void* p) {
    uint32_t a;
    asm("{ .reg .u64 t; cvta.to.shared.u64 t, %1; cvt.u32.u64 %0, t; }" : "=r"(a) : "l"(p));
    return a;
}
#define LDMX4(r, addr)                                                        \
    asm volatile("ldmatrix.sync.aligned.m8n8.x4.shared.b16 {%0,%1,%2,%3}, [%4];" \
        : "=r"((r)[0]), "=r"((r)[1]), "=r"((r)[2]), "=r"((r)[3]) : "r"(addr))
#define LDMX4_T(r, addr)                                                      \
    asm volatile("ldmatrix.sync.aligned.m8n8.x4.trans.shared.b16 {%0,%1,%2,%3}, [%4];" \
        : "=r"((r)[0]), "=r"((r)[1]), "=r"((r)[2]), "=r"((r)[3]) : "r"(addr))
#define MMA_BF16(c, a, b0, b1)                                                \
    asm volatile("mma.sync.aligned.m16n8k16.row.col.f32.bf16.bf16.f32 "       \
        "{%0,%1,%2,%3}, {%4,%5,%6,%7}, {%8,%9}, {%0,%1,%2,%3};"               \
        : "+f"((c)[0]), "+f"((c)[1]), "+f"((c)[2]), "+f"((c)[3])              \
        : "r"((a)[0]), "r"((a)[1]), "r"((a)[2]), "r"((a)[3]), "r"(b0), "r"(b1))

// ---------------------------------------------------------------------------
// Kernel A: A = att * mask
// ---------------------------------------------------------------------------
__global__ void prep_A(const float* __restrict__ att, const int* __restrict__ mask) {
    int i = blockIdx.x * blockDim.x + threadIdx.x;
    float4 a = reinterpret_cast<const float4*>(att)[i];
    int4   m = reinterpret_cast<const int4*>(mask)[i];
    float4 r;
    r.x = a.x * (float)m.x; r.y = a.y * (float)m.y;
    r.z = a.z * (float)m.z; r.w = a.w * (float)m.w;
    reinterpret_cast<float4*>(g_A)[i] = r;
}

// ---------------------------------------------------------------------------
// Kernel B: y = x/||x|| -> bf16 hi/lo ; v = x @ W -> bf16 hi/lo
// ---------------------------------------------------------------------------
__global__ void prep_xw(const float* __restrict__ x, const float* __restrict__ w) {
    __shared__ float sw[DD * DD];
    int tid = threadIdx.x;
    for (int i = tid; i < DD * DD; i += 256) sw[i] = w[i];
    __syncthreads();

    int warp = tid >> 5, lane = tid & 31;
    int row = blockIdx.x * 8 + warp;
    const float* xr = x + (size_t)row * DD;
    float x0 = xr[lane], x1 = xr[lane + 32];

    float ss = x0 * x0 + x1 * x1;
    #pragma unroll
    for (int o = 16; o; o >>= 1) ss += __shfl_xor_sync(0xffffffffu, ss, o);
    float inv = rsqrtf(fmaxf(ss, 1e-30f));

    float y0 = x0 * inv, y1 = x1 * inv;
    __nv_bfloat16 h0 = __float2bfloat16(y0), h1 = __float2bfloat16(y1);
    size_t rb = (size_t)row * DD;
    g_yh[rb + lane]      = h0;
    g_yh[rb + lane + 32] = h1;
    g_yl[rb + lane]      = __float2bfloat16(y0 - __bfloat162float(h0));
    g_yl[rb + lane + 32] = __float2bfloat16(y1 - __bfloat162float(h1));

    float a0 = 0.f, a1 = 0.f;
    #pragma unroll
    for (int d = 0; d < 32; ++d) {
        float xd = __shfl_sync(0xffffffffu, x0, d);
        a0 = fmaf(xd, sw[d * DD + lane],      a0);
        a1 = fmaf(xd, sw[d * DD + lane + 32], a1);
    }
    #pragma unroll
    for (int d = 0; d < 32; ++d) {
        float xd = __shfl_sync(0xffffffffu, x1, d);
        a0 = fmaf(xd, sw[(d + 32) * DD + lane],      a0);
        a1 = fmaf(xd, sw[(d + 32) * DD + lane + 32], a1);
    }
    __nv_bfloat16 v0 = __float2bfloat16(a0), v1 = __float2bfloat16(a1);
    g_vh[rb + lane]      = v0;
    g_vh[rb + lane + 32] = v1;
    g_vl[rb + lane]      = __float2bfloat16(a0 - __bfloat162float(v0));
    g_vl[rb + lane + 32] = __float2bfloat16(a1 - __bfloat162float(v1));
}

// ---------------------------------------------------------------------------
// Kernel C: full-tensor pipeline.
//   S = Yn.Ym^T (bf16-split mma) -> P = A*S split to bf16 hi/lo in smem
//   -> O += P.V (bf16-split mma, V frags via ldmatrix.trans).
//   CTA = (b, 128n tile); chunks of 64 m; 8 warps.
//   S-phase warp (wn,wm) = 32n x 32m subtile; O-phase warp w = 16n x 64e.
// ---------------------------------------------------------------------------
__global__ __launch_bounds__(256, 2)
void fused(const float* __restrict__ bias, float* __restrict__ out) {
    extern __shared__ char smc[];
    uint32_t sb = su32(smc);

    int b  = blockIdx.y;
    int n0 = blockIdx.x * 128;
    int tid = threadIdx.x;
    int w = tid >> 5, lane = tid & 31;
    int wn = w & 3, wm = w >> 2;
    int n0w = wn * 32, m0w = wm * 32;

    const __nv_bfloat16* yhB = g_yh + (size_t)b * NN * DD;
    const __nv_bfloat16* ylB = g_yl + (size_t)b * NN * DD;
    const __nv_bfloat16* vhB = g_vh + (size_t)b * NN * DD;
    const __nv_bfloat16* vlB = g_vl + (size_t)b * NN * DD;

    // Stage Yn tile (128 x 64 bf16 hi/lo), one-time
    #pragma unroll
    for (int k = 0; k < 4; ++k) {
        int idx = tid + k * 256;
        int r = idx >> 3, c = idx & 7;
        *reinterpret_cast<uint4*>(smc + OFF_YNH + r * YSTR + c * 16) =
            *reinterpret_cast<const uint4*>(yhB + (size_t)(n0 + r) * DD + c * 8);
        *reinterpret_cast<uint4*>(smc + OFF_YNL + r * YSTR + c * 16) =
            *reinterpret_cast<const uint4*>(ylB + (size_t)(n0 + r) * DD + c * 8);
    }

    // ldmatrix lane addressing
    int lrow = lane & 7, sub = lane >> 3;
    int rowoff = (sub & 1) * 8 + lrow;
    int koffb  = (sub >> 1) * 16;
    int t4 = lane >> 2, tm2 = (lane & 3) * 2;

    float ofr[8][4];                       // O fragments: 8 e-tiles x 4
    #pragma unroll
    for (int te = 0; te < 8; ++te)
        #pragma unroll
        for (int q = 0; q < 4; ++q) ofr[te][q] = 0.f;

    for (int m0 = 0; m0 < NN; m0 += 64) {
        __syncthreads();   // prior O-phase reads of sYm/sV/sP done

        // Stage Ym + V (64 x 64 bf16 hi/lo each)
        #pragma unroll
        for (int k = 0; k < 2; ++k) {
            int idx = tid + k * 256;
            int r = idx >> 3, c = idx & 7;
            size_t gofs = (size_t)(m0 + r) * DD + c * 8;
            uint32_t sofs = r * YSTR + c * 16;
            *reinterpret_cast<uint4*>(smc + OFF_YMH + sofs) =
                *reinterpret_cast<const uint4*>(yhB + gofs);
            *reinterpret_cast<uint4*>(smc + OFF_YML + sofs) =
                *reinterpret_cast<const uint4*>(ylB + gofs);
            *reinterpret_cast<uint4*>(smc + OFF_VH + sofs) =
                *reinterpret_cast<const uint4*>(vhB + gofs);
            *reinterpret_cast<uint4*>(smc + OFF_VL + sofs) =
                *reinterpret_cast<const uint4*>(vlB + gofs);
        }
        __syncthreads();

        // ---- S-phase: tensor mma, bf16 split (HH + HL + LH) ----
        float cfr[2][4][4];
        #pragma unroll
        for (int i = 0; i < 2; ++i)
            #pragma unroll
            for (int j = 0; j < 4; ++j)
                #pragma unroll
                for (int q = 0; q < 4; ++q) cfr[i][j][q] = 0.f;

        #pragma unroll
        for (int ks = 0; ks < 4; ++ks) {
            int kb = ks * 32 + koffb;
            uint32_t aH[2][4], aL[2][4], bH[2][4], bL[2][4];
            #pragma unroll
            for (int i = 0; i < 2; ++i) {
                uint32_t ra = (uint32_t)((n0w + i * 16 + rowoff) * YSTR + kb);
                LDMX4(aH[i], sb + OFF_YNH + ra);
                LDMX4(aL[i], sb + OFF_YNL + ra);
            }
            #pragma unroll
            for (int j16 = 0; j16 < 2; ++j16) {
                uint32_t rb2 = (uint32_t)((m0w + j16 * 16 + rowoff) * YSTR + kb);
                LDMX4(bH[j16], sb + OFF_YMH + rb2);
                LDMX4(bL[j16], sb + OFF_YML + rb2);
            }
            #pragma unroll
            for (int i = 0; i < 2; ++i)
                #pragma unroll
                for (int mt = 0; mt < 4; ++mt) {
                    int j16 = mt >> 1, par = mt & 1;
                    MMA_BF16(cfr[i][mt], aH[i], bH[j16][par], bH[j16][par + 2]);
                    MMA_BF16(cfr[i][mt], aH[i], bL[j16][par], bL[j16][par + 2]);
                    MMA_BF16(cfr[i][mt], aL[i], bH[j16][par], bH[j16][par + 2]);
                }
        }

        // ---- P-phase: P = A*S -> bf16 hi/lo into sPh/sPl [n][m] ----
        #pragma unroll
        for (int i = 0; i < 2; ++i) {
            #pragma unroll
            for (int mt = 0; mt < 4; ++mt) {
                int nfl = n0w + i * 16 + t4;
                int mfl = m0w + mt * 8 + tm2;
                const float* ar = g_A + (size_t)(n0 + nfl) * NN + (m0 + mfl);
                ull ap0 = *reinterpret_cast<const ull*>(ar);
                ull ap1 = *reinterpret_cast<const ull*>(ar + 8 * NN);
                float a0, a1, a2, a3;
                unpk(ap0, a0, a1);
                unpk(ap1, a2, a3);
                float p0 = cfr[i][mt][0] * a0, p1 = cfr[i][mt][1] * a1;
                float p2 = cfr[i][mt][2] * a2, p3 = cfr[i][mt][3] * a3;

                __nv_bfloat162 h01 = __float22bfloat162_rn(make_float2(p0, p1));
                float2 hf01 = __bfloat1622float2(h01);
                __nv_bfloat162 l01 =
                    __float22bfloat162_rn(make_float2(p0 - hf01.x, p1 - hf01.y));
                uint32_t o01 = (uint32_t)(nfl * YSTR + mfl * 2);
                *reinterpret_cast<__nv_bfloat162*>(smc + OFF_PH + o01) = h01;
                *reinterpret_cast<__nv_bfloat162*>(smc + OFF_PL + o01) = l01;

                __nv_bfloat162 h23 = __float22bfloat162_rn(make_float2(p2, p3));
                float2 hf23 = __bfloat1622float2(h23);
                __nv_bfloat162 l23 =
                    __float22bfloat162_rn(make_float2(p2 - hf23.x, p3 - hf23.y));
                uint32_t o23 = (uint32_t)((nfl + 8) * YSTR + mfl * 2);
                *reinterpret_cast<__nv_bfloat162*>(smc + OFF_PH + o23) = h23;
                *reinterpret_cast<__nv_bfloat162*>(smc + OFF_PL + o23) = l23;
            }
        }
        __syncthreads();

        // ---- O-phase: tensor mma, P(hi/lo) x V(hi/lo), 3 passes ----
        // warp w: n rows [w*16, w*16+16), e 0..63, k = m 0..63
        #pragma unroll
        for (int ks = 0; ks < 4; ++ks) {
            uint32_t pa = (uint32_t)((w * 16 + rowoff) * YSTR + ks * 32 + koffb);
            uint32_t aH[4], aL[4];
            LDMX4(aH, sb + OFF_PH + pa);
            LDMX4(aL, sb + OFF_PL + pa);
            #pragma unroll
            for (int eg = 0; eg < 4; ++eg) {
                uint32_t va = (uint32_t)((ks * 16 + rowoff) * YSTR + eg * 32 + koffb);
                uint32_t vH[4], vL[4];
                LDMX4_T(vH, sb + OFF_VH + va);
                LDMX4_T(vL, sb + OFF_VL + va);
                MMA_BF16(ofr[eg * 2],     aH, vH[0], vH[1]);
                MMA_BF16(ofr[eg * 2],     aH, vL[0], vL[1]);
                MMA_BF16(ofr[eg * 2],     aL, vH[0], vH[1]);
                MMA_BF16(ofr[eg * 2 + 1], aH, vH[2], vH[3]);
                MMA_BF16(ofr[eg * 2 + 1], aH, vL[2], vL[3]);
                MMA_BF16(ofr[eg * 2 + 1], aL, vH[2], vH[3]);
            }
        }
    }

    // ---- Epilogue: out[n][e] = O + bias  (fragment layout) ----
    float* ob = out + ((size_t)b * NN + n0) * DD;
    int nrow = w * 16 + t4;
    #pragma unroll
    for (int te = 0; te < 8; ++te) {
        int e = te * 8 + tm2;
        float bj0 = bias[e], bj1 = bias[e + 1];
        float2 v0 = make_float2(ofr[te][0] + bj0, ofr[te][1] + bj1);
        *reinterpret_cast<float2*>(ob + (size_t)nrow * DD + e) = v0;
        float2 v1 = make_float2(ofr[te][2] + bj0, ofr[te][3] + bj1);
        *reinterpret_cast<float2*>(ob + (size_t)(nrow + 8) * DD + e) = v1;
    }
}

// ---------------------------------------------------------------------------
extern "C" void kernel_launch(void* const* d_in, const int* in_sizes, int n_in,
                              void* d_out, int out_size) {
    const float* x    = (const float*)d_in[0];
    const float* w    = (const float*)d_in[1];
    const float* att  = (const float*)d_in[2];
    const float* bias = (const float*)d_in[3];
    const int*   mask = (const int*)d_in[4];
    float* out = (float*)d_out;

    prep_A<<<(NN * NN / 4) / 256, 256>>>(att, mask);
    prep_xw<<<(BB * NN) / 8, 256>>>(x, w);

    cudaFuncSetAttribute(fused, cudaFuncAttributeMaxDynamicSharedMemorySize, SMEM_BYTES);
    dim3 grid(NN / 128, BB);
    fused<<<grid, 256, SMEM_BYTES>>>(bias, out);
}

// round 11
// speedup vs baseline: 3.2349x; 1.0870x over previous
#include <cuda_runtime.h>
#include <cuda_bf16.h>
#include <cstdint>

#define BB 16
#define NN 2048
#define DD 64
// All bf16 tiles: exact 128-byte rows, XOR swizzle (unit ^= row&7). No padding.

// ---------------- scratch (__device__ globals) -----------------------------
__device__ __nv_bfloat16 g_yh[BB * NN * DD];   // normalized x, bf16 hi
__device__ __nv_bfloat16 g_yl[BB * NN * DD];   // normalized x, bf16 lo
__device__ __nv_bfloat16 g_vh[BB * NN * DD];   // support = x@W, bf16 hi
__device__ __nv_bfloat16 g_vl[BB * NN * DD];   // support = x@W, bf16 lo
__device__ float         g_A[NN * NN];         // att * mask

// ---------------- smem byte offsets (swizzled 128B-row tiles) --------------
#define OFF_YNH 0          // 128 x 128B                16384
#define OFF_YNL 16384      //                           16384
#define OFF_YMH 32768      // 2 bufs x (64 x 128B)      16384
#define OFF_YML 49152      //                           16384
#define OFF_VH  65536      // 64 x 128B                  8192
#define OFF_VL  73728      //                            8192
#define OFF_PH  81920      // 128 x 128B                16384
#define OFF_PL  98304      //                           16384
#define SMEM_BYTES 114688

typedef unsigned long long ull;
__device__ __forceinline__ void unpk(ull v, float& lo, float& hi) {
    asm("mov.b64 {%0, %1}, %2;" : "=f"(lo), "=f"(hi) : "l"(v));
}
__device__ __forceinline__ uint32_t su32(const void* p) {
    uint32_t a;
    asm("{ .reg .u64 t; cvta.to.shared.u64 t, %1; cvt.u32.u64 %0, t; }" : "=r"(a) : "l"(p));
    return a;
}
// swizzled address of 16B unit (row, unit) in a 128B-row tile
__device__ __forceinline__ uint32_t swu(uint32_t base, int row, int unit) {
    return base + row * 128 + ((unit ^ (row & 7)) << 4);
}
__device__ __forceinline__ void cpa16(uint32_t dst, const void* src) {
    asm volatile("cp.async.cg.shared.global [%0], [%1], 16;" :: "r"(dst), "l"(src));
}
#define CPA_COMMIT() asm volatile("cp.async.commit_group;" ::: "memory")
#define CPA_WAIT(N)  asm volatile("cp.async.wait_group %0;" :: "n"(N) : "memory")

#define LDMX4(r, addr)                                                        \
    asm volatile("ldmatrix.sync.aligned.m8n8.x4.shared.b16 {%0,%1,%2,%3}, [%4];" \
        : "=r"((r)[0]), "=r"((r)[1]), "=r"((r)[2]), "=r"((r)[3]) : "r"(addr))
#define LDMX4_T(r, addr)                                                      \
    asm volatile("ldmatrix.sync.aligned.m8n8.x4.trans.shared.b16 {%0,%1,%2,%3}, [%4];" \
        : "=r"((r)[0]), "=r"((r)[1]), "=r"((r)[2]), "=r"((r)[3]) : "r"(addr))
#define MMA_BF16(c, a, b0, b1)                                                \
    asm volatile("mma.sync.aligned.m16n8k16.row.col.f32.bf16.bf16.f32 "       \
        "{%0,%1,%2,%3}, {%4,%5,%6,%7}, {%8,%9}, {%0,%1,%2,%3};"               \
        : "+f"((c)[0]), "+f"((c)[1]), "+f"((c)[2]), "+f"((c)[3])              \
        : "r"((a)[0]), "r"((a)[1]), "r"((a)[2]), "r"((a)[3]), "r"(b0), "r"(b1))

// ---------------------------------------------------------------------------
// Kernel A: A = att * mask
// ---------------------------------------------------------------------------
__global__ void prep_A(const float* __restrict__ att, const int* __restrict__ mask) {
    int i = blockIdx.x * blockDim.x + threadIdx.x;
    float4 a = reinterpret_cast<const float4*>(att)[i];
    int4   m = reinterpret_cast<const int4*>(mask)[i];
    float4 r;
    r.x = a.x * (float)m.x; r.y = a.y * (float)m.y;
    r.z = a.z * (float)m.z; r.w = a.w * (float)m.w;
    reinterpret_cast<float4*>(g_A)[i] = r;
}

// ---------------------------------------------------------------------------
// Kernel B: y = x/||x|| -> bf16 hi/lo ; v = x @ W -> bf16 hi/lo
// ---------------------------------------------------------------------------
__global__ void prep_xw(const float* __restrict__ x, const float* __restrict__ w) {
    __shared__ float sw[DD * DD];
    int tid = threadIdx.x;
    for (int i = tid; i < DD * DD; i += 256) sw[i] = w[i];
    __syncthreads();

    int warp = tid >> 5, lane = tid & 31;
    int row = blockIdx.x * 8 + warp;
    const float* xr = x + (size_t)row * DD;
    float x0 = xr[lane], x1 = xr[lane + 32];

    float ss = x0 * x0 + x1 * x1;
    #pragma unroll
    for (int o = 16; o; o >>= 1) ss += __shfl_xor_sync(0xffffffffu, ss, o);
    float inv = rsqrtf(fmaxf(ss, 1e-30f));

    float y0 = x0 * inv, y1 = x1 * inv;
    __nv_bfloat16 h0 = __float2bfloat16(y0), h1 = __float2bfloat16(y1);
    size_t rb = (size_t)row * DD;
    g_yh[rb + lane]      = h0;
    g_yh[rb + lane + 32] = h1;
    g_yl[rb + lane]      = __float2bfloat16(y0 - __bfloat162float(h0));
    g_yl[rb + lane + 32] = __float2bfloat16(y1 - __bfloat162float(h1));

    float a0 = 0.f, a1 = 0.f;
    #pragma unroll
    for (int d = 0; d < 32; ++d) {
        float xd = __shfl_sync(0xffffffffu, x0, d);
        a0 = fmaf(xd, sw[d * DD + lane],      a0);
        a1 = fmaf(xd, sw[d * DD + lane + 32], a1);
    }
    #pragma unroll
    for (int d = 0; d < 32; ++d) {
        float xd = __shfl_sync(0xffffffffu, x1, d);
        a0 = fmaf(xd, sw[(d + 32) * DD + lane],      a0);
        a1 = fmaf(xd, sw[(d + 32) * DD + lane + 32], a1);
    }
    __nv_bfloat16 v0 = __float2bfloat16(a0), v1 = __float2bfloat16(a1);
    g_vh[rb + lane]      = v0;
    g_vh[rb + lane + 32] = v1;
    g_vl[rb + lane]      = __float2bfloat16(a0 - __bfloat162float(v0));
    g_vl[rb + lane + 32] = __float2bfloat16(a1 - __bfloat162float(v1));
}

// ---------------------------------------------------------------------------
// Kernel C: full-tensor pipeline, cp.async double-buffered staging.
//   S = Yn.Ym^T (bf16-split) -> P = A*S -> bf16 hi/lo -> O += P.V (bf16-split)
//   CTA = (b, 128n); 32 chunks of 64 m; Ym hi/lo double-buffered, V single.
// ---------------------------------------------------------------------------
__global__ __launch_bounds__(256, 2)
void fused(const float* __restrict__ bias, float* __restrict__ out) {
    extern __shared__ char smc[];
    uint32_t sb = su32(smc);

    int b  = blockIdx.y;
    int n0 = blockIdx.x * 128;
    int tid = threadIdx.x;
    int w = tid >> 5, lane = tid & 31;
    int wn = w & 3, wm = w >> 2;
    int n0w = wn * 32, m0w = wm * 32;

    const __nv_bfloat16* yhB = g_yh + (size_t)b * NN * DD;
    const __nv_bfloat16* ylB = g_yl + (size_t)b * NN * DD;
    const __nv_bfloat16* vhB = g_vh + (size_t)b * NN * DD;
    const __nv_bfloat16* vlB = g_vl + (size_t)b * NN * DD;

    // staging indices (8 threads per 128B row)
    int sr_base = tid >> 3, sc = tid & 7;

    // Stage Yn tile (128 x 64 bf16 hi/lo), one-time, swizzled
    #pragma unroll
    for (int k = 0; k < 4; ++k) {
        int r = sr_base + k * 32;
        uint32_t dof = swu(0, r, sc);
        size_t gof = (size_t)(n0 + r) * DD + sc * 8;
        *reinterpret_cast<uint4*>(smc + OFF_YNH + dof) =
            *reinterpret_cast<const uint4*>(yhB + gof);
        *reinterpret_cast<uint4*>(smc + OFF_YNL + dof) =
            *reinterpret_cast<const uint4*>(ylB + gof);
    }

    // Prologue: async-stage Ym(chunk 0) into buf 0
    #pragma unroll
    for (int k = 0; k < 2; ++k) {
        int r = sr_base + k * 32;
        uint32_t dof = swu(0, r, sc);
        size_t gof = (size_t)r * DD + sc * 8;
        cpa16(sb + OFF_YMH + dof, yhB + gof);
        cpa16(sb + OFF_YML + dof, ylB + gof);
    }
    CPA_COMMIT();

    // ldmatrix lane addressing
    int lrow = lane & 7, sub = lane >> 3;
    int rowoff = (sub & 1) * 8 + lrow;
    int usub   = sub >> 1;                  // k-unit half select
    int t4 = lane >> 2, tm2 = (lane & 3) * 2;

    float ofr[8][4];
    #pragma unroll
    for (int te = 0; te < 8; ++te)
        #pragma unroll
        for (int q = 0; q < 4; ++q) ofr[te][q] = 0.f;

    for (int c = 0; c < 32; ++c) {
        int m0 = c * 64;
        int buf = c & 1;

        // Issue next Ym (buf^1) + this chunk's V, one commit group
        #pragma unroll
        for (int k = 0; k < 2; ++k) {
            int r = sr_base + k * 32;
            uint32_t dof = swu(0, r, sc);
            if (c + 1 < 32) {
                size_t gof = (size_t)(m0 + 64 + r) * DD + sc * 8;
                uint32_t bo = (buf ^ 1) * 8192;
                cpa16(sb + OFF_YMH + bo + dof, yhB + gof);
                cpa16(sb + OFF_YML + bo + dof, ylB + gof);
            }
            size_t gv = (size_t)(m0 + r) * DD + sc * 8;
            cpa16(sb + OFF_VH + dof, vhB + gv);
            cpa16(sb + OFF_VL + dof, vlB + gv);
        }
        CPA_COMMIT();
        CPA_WAIT(1);          // Ym(c) landed (V(c) may still fly)
        __syncthreads();

        // ---- S-phase: tensor mma, bf16 split (HH + HL + LH) ----
        float cfr[2][4][4];
        #pragma unroll
        for (int i = 0; i < 2; ++i)
            #pragma unroll
            for (int j = 0; j < 4; ++j)
                #pragma unroll
                for (int q = 0; q < 4; ++q) cfr[i][j][q] = 0.f;

        uint32_t ymb = (uint32_t)(buf * 8192);
        #pragma unroll
        for (int ks = 0; ks < 4; ++ks) {
            int un = ks * 2 + usub;
            uint32_t aH[2][4], aL[2][4], bH[2][4], bL[2][4];
            #pragma unroll
            for (int i = 0; i < 2; ++i) {
                uint32_t ra = swu(0, n0w + i * 16 + rowoff, un);
                LDMX4(aH[i], sb + OFF_YNH + ra);
                LDMX4(aL[i], sb + OFF_YNL + ra);
            }
            #pragma unroll
            for (int j16 = 0; j16 < 2; ++j16) {
                uint32_t rb2 = swu(0, m0w + j16 * 16 + rowoff, un);
                LDMX4(bH[j16], sb + OFF_YMH + ymb + rb2);
                LDMX4(bL[j16], sb + OFF_YML + ymb + rb2);
            }
            #pragma unroll
            for (int i = 0; i < 2; ++i)
                #pragma unroll
                for (int mt = 0; mt < 4; ++mt) {
                    int j16 = mt >> 1, par = mt & 1;
                    MMA_BF16(cfr[i][mt], aH[i], bH[j16][par], bH[j16][par + 2]);
                    MMA_BF16(cfr[i][mt], aH[i], bL[j16][par], bL[j16][par + 2]);
                    MMA_BF16(cfr[i][mt], aL[i], bH[j16][par], bH[j16][par + 2]);
                }
        }

        // ---- P-phase: P = A*S -> bf16 hi/lo into sPh/sPl [n][m] (swizzled) ----
        #pragma unroll
        for (int i = 0; i < 2; ++i) {
            #pragma unroll
            for (int mt = 0; mt < 4; ++mt) {
                int nfl = n0w + i * 16 + t4;
                int mfl = m0w + mt * 8 + tm2;
                const float* ar = g_A + (size_t)(n0 + nfl) * NN + (m0 + mfl);
                ull ap0 = *reinterpret_cast<const ull*>(ar);
                ull ap1 = *reinterpret_cast<const ull*>(ar + 8 * NN);
                float a0, a1, a2, a3;
                unpk(ap0, a0, a1);
                unpk(ap1, a2, a3);
                float p0 = cfr[i][mt][0] * a0, p1 = cfr[i][mt][1] * a1;
                float p2 = cfr[i][mt][2] * a2, p3 = cfr[i][mt][3] * a3;

                int u = mfl >> 3;
                uint32_t o01 = (uint32_t)(nfl * 128 + (((u) ^ (nfl & 7)) << 4) + tm2 * 2);
                __nv_bfloat162 h01 = __float22bfloat162_rn(make_float2(p0, p1));
                float2 hf01 = __bfloat1622float2(h01);
                __nv_bfloat162 l01 =
                    __float22bfloat162_rn(make_float2(p0 - hf01.x, p1 - hf01.y));
                *reinterpret_cast<__nv_bfloat162*>(smc + OFF_PH + o01) = h01;
                *reinterpret_cast<__nv_bfloat162*>(smc + OFF_PL + o01) = l01;

                int nf8 = nfl + 8;
                uint32_t o23 = (uint32_t)(nf8 * 128 + (((u) ^ (nf8 & 7)) << 4) + tm2 * 2);
                __nv_bfloat162 h23 = __float22bfloat162_rn(make_float2(p2, p3));
                float2 hf23 = __bfloat1622float2(h23);
                __nv_bfloat162 l23 =
                    __float22bfloat162_rn(make_float2(p2 - hf23.x, p3 - hf23.y));
                *reinterpret_cast<__nv_bfloat162*>(smc + OFF_PH + o23) = h23;
                *reinterpret_cast<__nv_bfloat162*>(smc + OFF_PL + o23) = l23;
            }
        }
        CPA_WAIT(0);          // V(c) (and Ym(c+1)) landed
        __syncthreads();

        // ---- O-phase: tensor mma, P(hi/lo) x V(hi/lo), 3 passes ----
        #pragma unroll
        for (int ks = 0; ks < 4; ++ks) {
            int un = ks * 2 + usub;
            uint32_t pa = swu(0, w * 16 + rowoff, un);
            uint32_t aH[4], aL[4];
            LDMX4(aH, sb + OFF_PH + pa);
            LDMX4(aL, sb + OFF_PL + pa);
            #pragma unroll
            for (int eg = 0; eg < 4; ++eg) {
                uint32_t va = swu(0, ks * 16 + rowoff, eg * 2 + usub);
                uint32_t vH[4], vL[4];
                LDMX4_T(vH, sb + OFF_VH + va);
                LDMX4_T(vL, sb + OFF_VL + va);
                MMA_BF16(ofr[eg * 2],     aH, vH[0], vH[1]);
                MMA_BF16(ofr[eg * 2],     aH, vL[0], vL[1]);
                MMA_BF16(ofr[eg * 2],     aL, vH[0], vH[1]);
                MMA_BF16(ofr[eg * 2 + 1], aH, vH[2], vH[3]);
                MMA_BF16(ofr[eg * 2 + 1], aH, vL[2], vL[3]);
                MMA_BF16(ofr[eg * 2 + 1], aL, vH[2], vH[3]);
            }
        }
        __syncthreads();      // protect sP / V buf before next chunk's writes
    }

    // ---- Epilogue: out[n][e] = O + bias ----
    float* ob = out + ((size_t)b * NN + n0) * DD;
    int nrow = w * 16 + t4;
    #pragma unroll
    for (int te = 0; te < 8; ++te) {
        int e = te * 8 + tm2;
        float bj0 = bias[e], bj1 = bias[e + 1];
        float2 v0 = make_float2(ofr[te][0] + bj0, ofr[te][1] + bj1);
        *reinterpret_cast<float2*>(ob + (size_t)nrow * DD + e) = v0;
        float2 v1 = make_float2(ofr[te][2] + bj0, ofr[te][3] + bj1);
        *reinterpret_cast<float2*>(ob + (size_t)(nrow + 8) * DD + e) = v1;
    }
}

// ---------------------------------------------------------------------------
extern "C" void kernel_launch(void* const* d_in, const int* in_sizes, int n_in,
                              void* d_out, int out_size) {
    const float* x    = (const float*)d_in[0];
    const float* w    = (const float*)d_in[1];
    const float* att  = (const float*)d_in[2];
    const float* bias = (const float*)d_in[3];
    const int*   mask = (const int*)d_in[4];
    float* out = (float*)d_out;

    prep_A<<<(NN * NN / 4) / 256, 256>>>(att, mask);
    prep_xw<<<(BB * NN) / 8, 256>>>(x, w);

    cudaFuncSetAttribute(fused, cudaFuncAttributeMaxDynamicSharedMemorySize, SMEM_BYTES);
    dim3 grid(NN / 128, BB);
    fused<<<grid, 256, SMEM_BYTES>>>(bias, out);
}